// round 14
// baseline (speedup 1.0000x reference)
#include <cuda.h>
#include <cuda_runtime.h>

#define BB    2
#define NN    40000
#define C_IN  64
#define MM    40000
#define KNB   16
#define HH    8
#define C_MID 16

#define WARPS_PER_BLOCK 8
#define POINTS_TOTAL    (BB * MM)   // 80000

typedef unsigned long long ull;

__device__ __forceinline__ ull pack2(float lo, float hi) {
    ull r; asm("mov.b64 %0,{%1,%2};" : "=l"(r) : "f"(lo), "f"(hi)); return r;
}
__device__ __forceinline__ void unpack2(float& lo, float& hi, ull v) {
    asm("mov.b64 {%0,%1},%2;" : "=f"(lo), "=f"(hi) : "l"(v));
}
__device__ __forceinline__ void fma2(ull& d, ull a, ull b) {
    asm("fma.rn.f32x2 %0,%1,%2,%3;" : "=l"(d) : "l"(a), "l"(b), "l"(d));
}
__device__ __forceinline__ uint32_t smem_u32(const void* p) {
    uint32_t a;
    asm("{ .reg .u64 t; cvta.to.shared.u64 t, %1; cvt.u32.u64 %0, t; }" : "=r"(a) : "l"(p));
    return a;
}

// stage w[16][16] + g[16][8] for point p into wg buffer via cp.async (3x16B/lane)
__device__ __forceinline__ void stage_wg(uint32_t wb, const float* wnet,
                                         const float* guid, long long p, int lane) {
    const float4* w4 = (const float4*)(wnet + p * (KNB * C_MID));
    const float4* g4 = (const float4*)(guid + p * (KNB * HH));
    const uint32_t ws = wb + 16u * lane;
    asm volatile("cp.async.cg.shared.global [%0], [%1], 16;"
                 :: "r"(ws),          "l"(w4 + lane)      : "memory");
    asm volatile("cp.async.cg.shared.global [%0], [%1], 16;"
                 :: "r"(ws + 512u),   "l"(w4 + lane + 32) : "memory");
    asm volatile("cp.async.cg.shared.global [%0], [%1], 16;"
                 :: "r"(wb + 1024u + 16u * lane), "l"(g4 + lane) : "memory");
}

// gather 16 f rows (256B each) into fbuf via cp.async; commits 2 groups
__device__ __forceinline__ void gather_f(uint32_t fbuf, const float* feats,
                                         int myidx, int badd, int lane) {
    const char* fby = (const char*)feats;
    const int half = lane >> 4;
    const uint32_t fdst = fbuf + 16u * lane;
#pragma unroll
    for (int i = 0; i < 4; i++) {
        const int r0 = __shfl_sync(0xffffffffu, myidx, 2 * i);
        const int r1 = __shfl_sync(0xffffffffu, myidx, 2 * i + 1);
        const long long row = (long long)((half ? r1 : r0) + badd);
        asm volatile("cp.async.cg.shared.global [%0], [%1], 16;"
                     :: "r"(fdst + 512u * i),
                        "l"(fby + row * 256 + (lane & 15) * 16) : "memory");
    }
    asm volatile("cp.async.commit_group;" ::: "memory");
#pragma unroll
    for (int i = 4; i < 8; i++) {
        const int r0 = __shfl_sync(0xffffffffu, myidx, 2 * i);
        const int r1 = __shfl_sync(0xffffffffu, myidx, 2 * i + 1);
        const long long row = (long long)((half ? r1 : r0) + badd);
        asm volatile("cp.async.cg.shared.global [%0], [%1], 16;"
                     :: "r"(fdst + 512u * i),
                        "l"(fby + row * 256 + (lane & 15) * 16) : "memory");
    }
    asm volatile("cp.async.commit_group;" ::: "memory");
}

// k-loop: pure LDS + FMA2; waits remaining cp.async group at k==8
__device__ __forceinline__ void compute16(const float* f_sh, const float* g_sh,
                                          uint32_t wbase, ull* c0, ull* c1, int lane) {
#pragma unroll
    for (int k = 0; k < KNB; k++) {
        if (k == 8) {
            asm volatile("cp.async.wait_group 0;" ::: "memory");
            __syncwarp();
        }
        const float2 f = *(const float2*)(f_sh + k * 64 + lane * 2);
        const float  g = g_sh[k * HH + (lane >> 2)];
        const float a0 = f.x * g, a1 = f.y * g;
        const ull a00 = pack2(a0, a0);
        const ull a11 = pack2(a1, a1);

        ull w01, w23, w45, w67, w89, wab, wcd, wef;
        const uint32_t wa = wbase + k * (C_MID * 4);
        asm("ld.shared.v2.b64 {%0,%1}, [%2];"    : "=l"(w01), "=l"(w23) : "r"(wa));
        asm("ld.shared.v2.b64 {%0,%1}, [%2+16];" : "=l"(w45), "=l"(w67) : "r"(wa));
        asm("ld.shared.v2.b64 {%0,%1}, [%2+32];" : "=l"(w89), "=l"(wab) : "r"(wa));
        asm("ld.shared.v2.b64 {%0,%1}, [%2+48];" : "=l"(wcd), "=l"(wef) : "r"(wa));

        fma2(c0[0], a00, w01); fma2(c0[1], a00, w23);
        fma2(c0[2], a00, w45); fma2(c0[3], a00, w67);
        fma2(c0[4], a00, w89); fma2(c0[5], a00, wab);
        fma2(c0[6], a00, wcd); fma2(c0[7], a00, wef);
        fma2(c1[0], a11, w01); fma2(c1[1], a11, w23);
        fma2(c1[2], a11, w45); fma2(c1[3], a11, w67);
        fma2(c1[4], a11, w89); fma2(c1[5], a11, wab);
        fma2(c1[6], a11, wcd); fma2(c1[7], a11, wef);
    }
}

// SW128-swizzled STS + one TMA tensor store; leaves bulk read-wait to caller
__device__ __forceinline__ void epilogue(uint32_t tile, const ull* c0, const ull* c1,
                                         int lane, long long p, const CUtensorMap* tmap) {
    const uint32_t obase = tile + 128u * lane;
    const uint32_t lsw = (lane & 7);
#pragma unroll
    for (int j = 0; j < 8; j++) {
        const ull u0 = (j < 4) ? c0[2 * j]     : c1[2 * (j - 4)];
        const ull u1 = (j < 4) ? c0[2 * j + 1] : c1[2 * (j - 4) + 1];
        asm volatile("st.shared.v2.b64 [%0], {%1,%2};"
                     :: "r"(obase + 16u * ((uint32_t)j ^ lsw)), "l"(u0), "l"(u1));
    }
    __syncwarp();
    if (lane == 0) {
        const int row = (int)(p * 32);
        asm volatile("fence.proxy.async.shared::cta;" ::: "memory");
        asm volatile(
            "cp.async.bulk.tensor.2d.global.shared::cta.tile.bulk_group "
            "[%0, {%1, %2}], [%3];"
            :: "l"(tmap), "r"(0), "r"(row), "r"(tile)
            : "memory");
        asm volatile("cp.async.bulk.commit_group;" ::: "memory");
    }
}

// ============================ 2-point pipelined TMA kernel ============================
// Per warp: 2 consecutive points. Point B's idx LDG + w/g staging issued during
// point A's prologue (second 1.5KB wg buffer); f/epi tile (4KB) reused after
// TMA-A's smem read completes. smem 56KB/CTA, 4 CTAs/SM.
__global__ __launch_bounds__(256, 4)
void pcf_tma(const __grid_constant__ CUtensorMap tmap,
             const float* __restrict__ feats,  // [B,N,64]
             const int*   __restrict__ inds,   // [B,M,16] int32
             const float* __restrict__ guid,   // [B,M,16,8]
             const float* __restrict__ wnet)   // [B,M,16,16]
{
    __shared__ __align__(1024) float region[WARPS_PER_BLOCK][1024];  // 32KB f/epi
    __shared__ __align__(16)   float wg[WARPS_PER_BLOCK][768];       // 24KB wgA+wgB

    const int warp = threadIdx.x >> 5;
    const int lane = threadIdx.x & 31;
    const long long p0 = ((long long)blockIdx.x * WARPS_PER_BLOCK + warp) * 2;

    const uint32_t fbuf   = smem_u32(&region[warp][0]);
    const uint32_t wbaseA = smem_u32(&wg[warp][0]);
    const uint32_t wbaseB = wbaseA + 1536u;
    const float*   g_shA  = &wg[warp][256];
    const float*   g_shB  = &wg[warp][640];
    const float*   f_sh   = &region[warp][0];

    // ---- prologue: BOTH points' idx + w/g staged up front ----
    int idxA = 0, idxB = 0;
    if (lane < KNB) {
        idxA = inds[p0 * KNB + lane];
        idxB = inds[(p0 + 1) * KNB + lane];
    }
    stage_wg(wbaseA, wnet, guid, p0, lane);
    stage_wg(wbaseB, wnet, guid, p0 + 1, lane);

    const int badd = (p0 >= MM) ? NN : 0;   // pair never straddles batch (MM even)

    gather_f(fbuf, feats, idxA, badd, lane);   // groups: G1=wgA+wgB+fA0-7, G0=fA8-15

    ull c0[8], c1[8];
#pragma unroll
    for (int j = 0; j < 8; j++) { c0[j] = 0ull; c1[j] = 0ull; }

    asm volatile("cp.async.wait_group 1;" ::: "memory");
    __syncwarp();
    compute16(f_sh, g_shA, wbaseA, c0, c1, lane);

    __syncwarp();                              // all lanes done reading fA
    epilogue(fbuf, c0, c1, lane, p0, &tmap);   // TMA store A (committed, not waited)

    // reuse tile for B: TMA-A must finish READING smem first
    if (lane == 0)
        asm volatile("cp.async.bulk.wait_group.read 0;" ::: "memory");
    __syncwarp();

    gather_f(fbuf, feats, idxB, badd, lane);   // wgB already resident

#pragma unroll
    for (int j = 0; j < 8; j++) { c0[j] = 0ull; c1[j] = 0ull; }

    asm volatile("cp.async.wait_group 1;" ::: "memory");
    __syncwarp();
    compute16(f_sh, g_shB, wbaseB, c0, c1, lane);

    __syncwarp();
    epilogue(fbuf, c0, c1, lane, p0 + 1, &tmap);

    if (lane == 0)
        asm volatile("cp.async.bulk.wait_group.read 0;" ::: "memory");
}

// ============================ fallback (R3, 102us) ============================
#define REGION_F 1152
__device__ __forceinline__ ull mul2_(ull a, ull b) {
    ull r; asm("mul.rn.f32x2 %0,%1,%2;" : "=l"(r) : "l"(a), "l"(b)); return r;
}

__global__ __launch_bounds__(256, 4)
void pcf_fallback(const float* __restrict__ feats, const int* __restrict__ inds,
                  const float* __restrict__ guid, const float* __restrict__ wnet,
                  float* __restrict__ out)
{
    __shared__ float region[WARPS_PER_BLOCK][REGION_F];
    const int warp = threadIdx.x >> 5;
    const int lane = threadIdx.x & 31;
    const long long p = (long long)blockIdx.x * WARPS_PER_BLOCK + warp;

    float* w_sh = &region[warp][0];
    float* g_sh = &region[warp][256];

    int myidx = 0;
    if (lane < KNB) myidx = inds[p * KNB + lane];
    {
        const float4* w4 = (const float4*)(wnet + p * (KNB * C_MID));
        float4* ws4 = (float4*)w_sh;
        ws4[lane]      = w4[lane];
        ws4[lane + 32] = w4[lane + 32];
        const float4* g4 = (const float4*)(guid + p * (KNB * HH));
        ((float4*)g_sh)[lane] = g4[lane];
    }
    __syncwarp();

    const long long b = p / MM;
    const float2* fbase = (const float2*)feats + b * (long long)NN * (C_IN / 2);

    ull acc[C_MID];
#pragma unroll
    for (int d = 0; d < C_MID; d++) acc[d] = 0ull;

#pragma unroll
    for (int k = 0; k < KNB; k++) {
        const int nidx = __shfl_sync(0xffffffffu, myidx, k);
        const float2 f = fbase[(long long)nidx * (C_IN / 2) + lane];
        const float  g = g_sh[k * HH + (lane >> 2)];
        const ull a2 = mul2_(pack2(f.x, f.y), pack2(g, g));
        const float4 w0 = ((const float4*)(w_sh + k * C_MID))[0];
        const float4 w1 = ((const float4*)(w_sh + k * C_MID))[1];
        const float4 w2 = ((const float4*)(w_sh + k * C_MID))[2];
        const float4 w3 = ((const float4*)(w_sh + k * C_MID))[3];
        fma2(acc[0],  a2, pack2(w0.x, w0.x)); fma2(acc[1],  a2, pack2(w0.y, w0.y));
        fma2(acc[2],  a2, pack2(w0.z, w0.z)); fma2(acc[3],  a2, pack2(w0.w, w0.w));
        fma2(acc[4],  a2, pack2(w1.x, w1.x)); fma2(acc[5],  a2, pack2(w1.y, w1.y));
        fma2(acc[6],  a2, pack2(w1.z, w1.z)); fma2(acc[7],  a2, pack2(w1.w, w1.w));
        fma2(acc[8],  a2, pack2(w2.x, w2.x)); fma2(acc[9],  a2, pack2(w2.y, w2.y));
        fma2(acc[10], a2, pack2(w2.z, w2.z)); fma2(acc[11], a2, pack2(w2.w, w2.w));
        fma2(acc[12], a2, pack2(w3.x, w3.x)); fma2(acc[13], a2, pack2(w3.y, w3.y));
        fma2(acc[14], a2, pack2(w3.z, w3.z)); fma2(acc[15], a2, pack2(w3.w, w3.w));
    }

    __syncwarp();
    float4* b4 = (float4*)&region[warp][0];
#pragma unroll
    for (int j = 0; j < 4; j++) {
        float l0, h0, l1, h1, l2, h2, l3, h3;
        unpack2(l0, h0, acc[4*j + 0]); unpack2(l1, h1, acc[4*j + 1]);
        unpack2(l2, h2, acc[4*j + 2]); unpack2(l3, h3, acc[4*j + 3]);
        b4[9 * lane + j]     = make_float4(l0, l1, l2, l3);
        b4[9 * lane + 4 + j] = make_float4(h0, h1, h2, h3);
    }
    __syncwarp();

    float4* og = (float4*)(out + p * (C_IN * C_MID));
#pragma unroll
    for (int i = 0; i < 8; i++) {
        const int L4 = 32 * i + lane;
        og[L4] = b4[9 * (L4 >> 3) + (L4 & 7)];
    }
}

// ============================ host launcher ============================
typedef CUresult (*EncodeFn)(CUtensorMap*, CUtensorMapDataType, cuuint32_t, void*,
                             const cuuint64_t*, const cuuint64_t*,
                             const cuuint32_t*, const cuuint32_t*,
                             CUtensorMapInterleave, CUtensorMapSwizzle,
                             CUtensorMapL2promotion, CUtensorMapFloatOOBfill);

extern "C" void kernel_launch(void* const* d_in, const int* in_sizes, int n_in,
                              void* d_out, int out_size)
{
    const float* feats = (const float*)d_in[0];
    const int*   inds  = (const int*)d_in[1];
    const float* guid  = (const float*)d_in[2];
    const float* wnet  = (const float*)d_in[3];

    void* fn = nullptr;
    cudaDriverEntryPointQueryResult qres;
    bool ok = (cudaGetDriverEntryPoint("cuTensorMapEncodeTiled", &fn,
                                       cudaEnableDefault, &qres) == cudaSuccess) && fn;
    CUtensorMap tmap;
    if (ok) {
        cuuint64_t dims[2]    = { 32ull, (cuuint64_t)POINTS_TOTAL * 32ull };
        cuuint64_t strides[1] = { 128ull };
        cuuint32_t box[2]     = { 32u, 32u };
        cuuint32_t estr[2]    = { 1u, 1u };
        CUresult r = ((EncodeFn)fn)(&tmap, CU_TENSOR_MAP_DATA_TYPE_FLOAT32, 2, d_out,
                                    dims, strides, box, estr,
                                    CU_TENSOR_MAP_INTERLEAVE_NONE,
                                    CU_TENSOR_MAP_SWIZZLE_128B,
                                    CU_TENSOR_MAP_L2_PROMOTION_L2_128B,
                                    CU_TENSOR_MAP_FLOAT_OOB_FILL_NONE);
        ok = (r == CUDA_SUCCESS);
    }

    if (ok) {
        const int blocks = POINTS_TOTAL / (WARPS_PER_BLOCK * 2); // 5000
        pcf_tma<<<blocks, 256>>>(tmap, feats, inds, guid, wnet);
    } else {
        const int blocks = POINTS_TOTAL / WARPS_PER_BLOCK;       // 10000
        pcf_fallback<<<blocks, 256>>>(feats, inds, guid, wnet, (float*)d_out);
    }
}